// round 5
// baseline (speedup 1.0000x reference)
#include <cuda_runtime.h>
#include <math.h>
#include <stdint.h>

#define HID 128
#define BMT 128      // edges on tensor warps
#define BMF 64       // edges on fma warps
#define TILE 192
#define THREADS 384
#define NPB 32
#define N_NODES_MAX 100000

__device__ float g_node_emb[N_NODES_MAX * HID];
__device__ float g_w1p[8 * 4096];   // W1 chunks, mma layout, tf32-rounded
__device__ float g_w2p[4 * 4096];   // W2 chunks

__device__ __forceinline__ float tf32r(float v) {
    float o; asm("cvt.rna.tf32.f32 %0, %1;" : "=f"(o) : "f"(v)); return o;
}
__device__ __forceinline__ float silu(float v) {
    return __fdividef(v, 1.0f + __expf(-v));
}
__device__ __forceinline__ void mma8(float4& d,
                                     uint32_t a0, uint32_t a1, uint32_t a2, uint32_t a3,
                                     uint32_t b0, uint32_t b1) {
    asm volatile(
        "mma.sync.aligned.m16n8k8.row.col.f32.tf32.tf32.f32 "
        "{%0,%1,%2,%3},{%4,%5,%6,%7},{%8,%9},{%0,%1,%2,%3};"
        : "+f"(d.x), "+f"(d.y), "+f"(d.z), "+f"(d.w)
        : "r"(a0), "r"(a1), "r"(a2), "r"(a3), "r"(b0), "r"(b1));
}
__device__ __forceinline__ float2 ffma2(float2 a, float2 b, float2 c) {
    unsigned long long ua = *reinterpret_cast<unsigned long long*>(&a);
    unsigned long long ub = *reinterpret_cast<unsigned long long*>(&b);
    unsigned long long uc = *reinterpret_cast<unsigned long long*>(&c);
    unsigned long long ud;
    asm("fma.rn.f32x2 %0, %1, %2, %3;" : "=l"(ud) : "l"(ua), "l"(ub), "l"(uc));
    return *reinterpret_cast<float2*>(&ud);
}

#define BART() asm volatile("bar.sync 1, 256;" ::: "memory")
#define BARF() asm volatile("bar.sync 2, 128;" ::: "memory")

// ------------------- Kernel A: node embeddings ------------------------------
__global__ void node_emb_kernel(const float* __restrict__ x,
                                const float* __restrict__ pos,
                                const float* __restrict__ Wa,
                                const float* __restrict__ ba,
                                const float* __restrict__ Wp,
                                const float* __restrict__ bp, int N) {
    int j = threadIdx.x;
    float wa[16];
#pragma unroll
    for (int k = 0; k < 16; k++) wa[k] = Wa[k * HID + j];
    float wp[3];
#pragma unroll
    for (int k = 0; k < 3; k++) wp[k] = Wp[k * HID + j];
    float bb = ba[j] + bp[j];

    __shared__ float xs[NPB][16];
    __shared__ float ps[NPB][3];
    int n0 = blockIdx.x * NPB;
    for (int i = j; i < NPB * 16; i += 128) {
        int n = n0 + (i >> 4);
        xs[i >> 4][i & 15] = (n < N) ? x[n * 16 + (i & 15)] : 0.0f;
    }
    for (int i = j; i < NPB * 3; i += 128) {
        int n = n0 + i / 3;
        ps[i / 3][i % 3] = (n < N) ? pos[n * 3 + i % 3] : 0.0f;
    }
    __syncthreads();
    for (int n = 0; n < NPB; n++) {
        if (n0 + n >= N) break;
        float s = bb;
#pragma unroll
        for (int k = 0; k < 16; k++) s += xs[n][k] * wa[k];
#pragma unroll
        for (int k = 0; k < 3; k++) s += ps[n][k] * wp[k];
        g_node_emb[(n0 + n) * HID + j] = s;
    }
}

// ------------- Kernel B: weight images in mma layout, tf32-rounded ---------
__global__ void prep_weights(const float* __restrict__ W1,
                             const float* __restrict__ W2) {
    int c = blockIdx.x;                       // 0..7 -> W1, 8..11 -> W2
    const float* W = (c < 8) ? W1 : W2;
    int cc = (c < 8) ? c : c - 8;
    float* dst = (c < 8) ? (g_w1p + c * 4096) : (g_w2p + (c - 8) * 4096);
    for (int idx = threadIdx.x; idx < 4096; idx += 256) {
        int kg2 = idx >> 11;
        int rem = idx & 2047;
        int n = rem >> 4;
        int t = rem & 15;
        int jj = t >> 2, ii = t & 3;
        int kl = kg2 * 16 + ii * 4 + jj;
        dst[idx] = tf32r(W[(cc * 32 + kl) * 128 + n]);
    }
}

// ------------------- Kernel C: hybrid tensor+fma edge MLP -------------------
__global__ void __launch_bounds__(THREADS, 1)
edge_mlp_hybrid(const float* __restrict__ pos, const int* __restrict__ ei,
                const float* __restrict__ W1, const float* __restrict__ b1,
                const float* __restrict__ W2, const float* __restrict__ b2,
                const float* __restrict__ W3, const float* __restrict__ b3,
                float* __restrict__ out, int E) {
    extern __shared__ __align__(16) float sm[];
    float* XT = sm;              // 16384: A dbl-buf (8192) then hs then partials
    float* YT = sm + 16384;      // 8192:  B dbl-buf
    float* HF = sm + 24576;      // 8192:  fma h  [col 128][row 64]
    float* AF = sm + 32768;      // 1024:  fma A dbl-buf (8k x 64)
    float* BF = sm + 33792;      // 2048:  fma B dbl-buf (8k x 128)
    float* aux = sm + 35840;
    int*   s_soff_t = (int*)aux;            // 128
    int*   s_doff_t = (int*)(aux + 128);    // 128
    float* s_dist_t = aux + 256;            // 128
    int*   s_soff_f = (int*)(aux + 384);    // 64
    int*   s_doff_f = (int*)(aux + 448);    // 64
    float* s_dist_f = aux + 512;            // 64
    float* s_w256   = aux + 576;            // 128
    float* s_b1     = aux + 704;            // 128
    float* s_b2     = aux + 832;            // 128
    float* w3s      = aux + 960;            // 512
    float* b3s      = aux + 1472;           // 4

    const int tid = threadIdx.x;
    const int tile0 = blockIdx.x * TILE;

    // ---- cooperative setup ----
    if (tid < 128) {
        int ge = tile0 + tid; if (ge >= E) ge = E - 1;
        int s = ei[ge], d = ei[E + ge];
        s_soff_t[tid] = s * HID;
        s_doff_t[tid] = d * HID;
        float dx = pos[s * 3 + 0] - pos[d * 3 + 0];
        float dy = pos[s * 3 + 1] - pos[d * 3 + 1];
        float dz = pos[s * 3 + 2] - pos[d * 3 + 2];
        s_dist_t[tid] = sqrtf(dx * dx + dy * dy + dz * dz);
    } else if (tid < 192) {
        int j = tid - 128;
        int ge = tile0 + 128 + j; if (ge >= E) ge = E - 1;
        int s = ei[ge], d = ei[E + ge];
        s_soff_f[j] = s * HID;
        s_doff_f[j] = d * HID;
        float dx = pos[s * 3 + 0] - pos[d * 3 + 0];
        float dy = pos[s * 3 + 1] - pos[d * 3 + 1];
        float dz = pos[s * 3 + 2] - pos[d * 3 + 2];
        s_dist_f[j] = sqrtf(dx * dx + dy * dy + dz * dz);
    } else if (tid < 320) {
        int c = tid - 192;
        s_w256[c] = W1[256 * 128 + c];
        s_b1[c] = b1[c];
        s_b2[c] = b2[c];
    }
    for (int i = tid; i < 512; i += THREADS) w3s[i] = W3[i];
    if (tid < 4) b3s[tid] = b3[tid];
    __syncthreads();   // last whole-block sync; groups diverge below

    if (tid < 256) {
        // =================== TENSOR GROUP (8 warps, 128 edges) =============
        const int lane = tid & 31;
        const int wid  = tid >> 5;           // 0..7
        const int m_warp = (wid >> 2) * 64;  // 0 / 64
        const int n_warp = (wid & 3) * 32;
        const int grow = tid & 127;
        const int gkg2 = tid >> 7;           // 0/1
        const int gxo  = (grow >> 1) & 3;
        const int fxo  = (lane & 3) ^ ((lane >> 3) & 3);

        float4 acc[4][4];
#pragma unroll
        for (int i = 0; i < 4; i++)
#pragma unroll
            for (int j = 0; j < 4; j++) acc[i][j] = make_float4(0.f, 0.f, 0.f, 0.f);

        auto loadA = [&](int c, float4* v) {
            int kbase = (c & 3) * 32;
            const int* offs = (c < 4) ? s_soff_t : s_doff_t;
            const float* g = g_node_emb + offs[grow] + kbase + gkg2 * 16;
            float4 r0 = *reinterpret_cast<const float4*>(g + 0);
            float4 r1 = *reinterpret_cast<const float4*>(g + 4);
            float4 r2 = *reinterpret_cast<const float4*>(g + 8);
            float4 r3 = *reinterpret_cast<const float4*>(g + 12);
            v[0] = make_float4(tf32r(r0.x), tf32r(r1.x), tf32r(r2.x), tf32r(r3.x));
            v[1] = make_float4(tf32r(r0.y), tf32r(r1.y), tf32r(r2.y), tf32r(r3.y));
            v[2] = make_float4(tf32r(r0.z), tf32r(r1.z), tf32r(r2.z), tf32r(r3.z));
            v[3] = make_float4(tf32r(r0.w), tf32r(r1.w), tf32r(r2.w), tf32r(r3.w));
        };
        auto storeA = [&](float* Ab, const float4* v) {
            float4* d4 = reinterpret_cast<float4*>(Ab + gkg2 * 2048 + grow * 16);
#pragma unroll
            for (int j = 0; j < 4; j++) d4[j ^ gxo] = v[j];
        };
        auto loadB = [&](const float* gsrc, float4* v) {
            const float4* s4 = reinterpret_cast<const float4*>(gsrc);
#pragma unroll
            for (int i = 0; i < 4; i++) v[i] = s4[tid + 256 * i];
        };
        auto storeB = [&](float* Bb, const float4* v) {
            float4* d4 = reinterpret_cast<float4*>(Bb);
#pragma unroll
            for (int i = 0; i < 4; i++) d4[tid + 256 * i] = v[i];
        };
        auto compute_chunk = [&](const float* Ab, const float* Bb) {
#pragma unroll
            for (int kg2 = 0; kg2 < 2; kg2++) {
                const float4* A4 = reinterpret_cast<const float4*>(Ab + kg2 * 2048);
                const float4* B4 = reinterpret_cast<const float4*>(Bb + kg2 * 2048);
                float4 bv[4];
#pragma unroll
                for (int ni = 0; ni < 4; ni++) {
                    int n = n_warp + ni * 8 + (lane >> 2);
                    bv[ni] = B4[n * 4 + (lane & 3)];
                }
#pragma unroll
                for (int mi = 0; mi < 4; mi++) {
                    int r = m_warp + mi * 16 + (lane >> 2);
                    float4 vlo = A4[r * 4 + fxo];
                    float4 vhi = A4[(r + 8) * 4 + fxo];
#pragma unroll
                    for (int ni = 0; ni < 4; ni++) {
                        mma8(acc[mi][ni],
                             __float_as_uint(vlo.x), __float_as_uint(vhi.x),
                             __float_as_uint(vlo.y), __float_as_uint(vhi.y),
                             __float_as_uint(bv[ni].x), __float_as_uint(bv[ni].y));
                        mma8(acc[mi][ni],
                             __float_as_uint(vlo.z), __float_as_uint(vhi.z),
                             __float_as_uint(vlo.w), __float_as_uint(vhi.w),
                             __float_as_uint(bv[ni].z), __float_as_uint(bv[ni].w));
                    }
                }
            }
        };

        // -------- GEMM1: K=256 --------
        {
            float4 av[4], bvv[4];
            loadA(0, av); loadB(g_w1p, bvv);
            storeA(XT, av); storeB(YT, bvv);
        }
        BART();
        int p = 0;
#pragma unroll 1
        for (int c = 0; c < 8; c++) {
            float4 av[4], bvv[4];
            if (c < 7) { loadA(c + 1, av); loadB(g_w1p + (c + 1) * 4096, bvv); }
            compute_chunk(XT + p * 4096, YT + p * 4096);
            if (c < 7) {
                storeA(XT + (p ^ 1) * 4096, av);
                storeB(YT + (p ^ 1) * 4096, bvv);
                BART();
                p ^= 1;
            }
        }
        BART();

        // -------- epilogue1: h1 -> XT (A-fragment layout), prefetch W2c0 ----
        {
            float4 bvv[4];
            loadB(g_w2p, bvv);
#pragma unroll
            for (int mi = 0; mi < 4; mi++) {
                int r = m_warp + mi * 16 + (lane >> 2);
                float d0 = s_dist_t[r], d1 = s_dist_t[r + 8];
#pragma unroll
                for (int ni = 0; ni < 4; ni++) {
                    int c0 = n_warp + ni * 8 + ((lane & 3) << 1);
                    float w0 = s_w256[c0], w1 = s_w256[c0 + 1];
                    float bb0 = s_b1[c0], bb1 = s_b1[c0 + 1];
                    float4 a = acc[mi][ni];
                    float v0 = tf32r(silu(a.x + d0 * w0 + bb0));
                    float v1 = tf32r(silu(a.y + d0 * w1 + bb1));
                    float v2 = tf32r(silu(a.z + d1 * w0 + bb0));
                    float v3 = tf32r(silu(a.w + d1 * w1 + bb1));
#pragma unroll
                    for (int e = 0; e < 4; e++) {
                        int kc = c0 + (e & 1);
                        int m  = r + ((e >> 1) << 3);
                        float vv = (e == 0) ? v0 : (e == 1) ? v1 : (e == 2) ? v2 : v3;
                        int chunk = kc >> 5, kg2 = (kc >> 4) & 1, k16 = kc & 15;
                        int jj = k16 & 3, ii = k16 >> 2;
                        XT[chunk * 4096 + kg2 * 2048 + m * 16 +
                           ((jj ^ ((m >> 1) & 3)) << 2) + ii] = vv;
                    }
                    acc[mi][ni] = make_float4(0.f, 0.f, 0.f, 0.f);
                }
            }
            storeB(YT, bvv);
        }
        BART();

        // -------- GEMM2: K=128 --------
        int q = 0;
#pragma unroll 1
        for (int c = 0; c < 4; c++) {
            float4 bvv[4];
            if (c < 3) loadB(g_w2p + (c + 1) * 4096, bvv);
            compute_chunk(XT + c * 4096, YT + q * 4096);
            if (c < 3) {
                storeB(YT + (q ^ 1) * 4096, bvv);
                BART();
                q ^= 1;
            }
        }
        BART();

        // -------- epilogue2: silu(D2+b2) -> GEMM3 partials in XT ------------
        {
            const int cid = (wid & 3) * 4 + (lane & 3);
#pragma unroll
            for (int mi = 0; mi < 4; mi++) {
                int r = m_warp + mi * 16 + (lane >> 2);
                float4 plo = make_float4(0.f, 0.f, 0.f, 0.f);
                float4 phi = make_float4(0.f, 0.f, 0.f, 0.f);
#pragma unroll
                for (int ni = 0; ni < 4; ni++) {
                    int c0 = n_warp + ni * 8 + ((lane & 3) << 1);
                    float4 a = acc[mi][ni];
                    float v0 = silu(a.x + s_b2[c0]);
                    float v1 = silu(a.y + s_b2[c0 + 1]);
                    float v2 = silu(a.z + s_b2[c0]);
                    float v3 = silu(a.w + s_b2[c0 + 1]);
                    float4 w0 = *reinterpret_cast<const float4*>(&w3s[c0 * 4]);
                    float4 w1 = *reinterpret_cast<const float4*>(&w3s[(c0 + 1) * 4]);
                    plo.x += v0 * w0.x + v1 * w1.x;
                    plo.y += v0 * w0.y + v1 * w1.y;
                    plo.z += v0 * w0.z + v1 * w1.z;
                    plo.w += v0 * w0.w + v1 * w1.w;
                    phi.x += v2 * w0.x + v3 * w1.x;
                    phi.y += v2 * w0.y + v3 * w1.y;
                    phi.z += v2 * w0.z + v3 * w1.z;
                    phi.w += v2 * w0.w + v3 * w1.w;
                }
                *reinterpret_cast<float4*>(&XT[cid * 520 + r * 4]) = plo;
                *reinterpret_cast<float4*>(&XT[cid * 520 + (r + 8) * 4]) = phi;
            }
        }
        BART();
        if (tid < 128) {
            float4 o = make_float4(b3s[0], b3s[1], b3s[2], b3s[3]);
#pragma unroll
            for (int cid = 0; cid < 16; cid++) {
                float4 pv = *reinterpret_cast<const float4*>(&XT[cid * 520 + tid * 4]);
                o.x += pv.x; o.y += pv.y; o.z += pv.z; o.w += pv.w;
            }
            int ge = tile0 + tid;
            if (ge < E) *reinterpret_cast<float4*>(&out[ge * 4]) = o;
        }
    } else {
        // =================== FMA GROUP (4 warps, 64 edges) ==================
        const int ft  = tid - 256;          // 0..127
        const int ftx = ft & 15;            // col group (8 cols)
        const int fty = ft >> 4;            // row group (8 rows), 0..7
        const int growf = ft & 63;
        const int gkf   = (ft >> 6) << 2;   // 0 or 4
        const int srcOff = s_soff_f[growf];
        const int dstOff = s_doff_f[growf];
        const int fty8 = fty * 8;
        const int cAf  = ftx * 8;
        const int browf = ft >> 4;          // 0..7
        const int bcolf = (ft & 15) << 3;   // 0..120

        float2 acc[8][4];
#pragma unroll
        for (int i = 0; i < 8; i++)
#pragma unroll
            for (int j = 0; j < 4; j++) acc[i][j] = make_float2(0.f, 0.f);

        auto computeF = [&](const float* Ab, const float* Bb) {
#pragma unroll
            for (int kk = 0; kk < 8; kk++) {
                float4 a0 = *reinterpret_cast<const float4*>(&Ab[kk * 64 + fty8]);
                float4 a1 = *reinterpret_cast<const float4*>(&Ab[kk * 64 + fty8 + 4]);
                float4 b0 = *reinterpret_cast<const float4*>(&Bb[kk * 128 + cAf]);
                float4 b1v = *reinterpret_cast<const float4*>(&Bb[kk * 128 + cAf + 4]);
                float  ar[8]  = {a0.x, a0.y, a0.z, a0.w, a1.x, a1.y, a1.z, a1.w};
                float2 bp2[4] = {{b0.x, b0.y}, {b0.z, b0.w}, {b1v.x, b1v.y}, {b1v.z, b1v.w}};
#pragma unroll
                for (int i = 0; i < 8; i++) {
                    float2 ap = make_float2(ar[i], ar[i]);
#pragma unroll
                    for (int j = 0; j < 4; j++) acc[i][j] = ffma2(ap, bp2[j], acc[i][j]);
                }
            }
        };

        // -------- GEMM1: K=256 --------
        {
            float4 a = *reinterpret_cast<const float4*>(&g_node_emb[srcOff + gkf]);
            AF[(gkf + 0) * 64 + growf] = a.x;
            AF[(gkf + 1) * 64 + growf] = a.y;
            AF[(gkf + 2) * 64 + growf] = a.z;
            AF[(gkf + 3) * 64 + growf] = a.w;
            float4 b0 = *reinterpret_cast<const float4*>(&W1[browf * HID + bcolf]);
            float4 b1v = *reinterpret_cast<const float4*>(&W1[browf * HID + bcolf + 4]);
            *reinterpret_cast<float4*>(&BF[browf * 128 + bcolf]) = b0;
            *reinterpret_cast<float4*>(&BF[browf * 128 + bcolf + 4]) = b1v;
        }
        BARF();
        int p = 0;
#pragma unroll 1
        for (int kb = 0; kb < 256; kb += 8) {
            float4 an, bn0, bn1;
            const bool hn = (kb + 8) < 256;
            if (hn) {
                int k0 = kb + 8 + gkf;
                const float* gb = (k0 < 128) ? &g_node_emb[srcOff + k0]
                                             : &g_node_emb[dstOff + k0 - 128];
                an = *reinterpret_cast<const float4*>(gb);
                bn0 = *reinterpret_cast<const float4*>(&W1[(kb + 8 + browf) * HID + bcolf]);
                bn1 = *reinterpret_cast<const float4*>(&W1[(kb + 8 + browf) * HID + bcolf + 4]);
            }
            computeF(AF + p * 512, BF + p * 1024);
            if (hn) {
                float* Ad = AF + (p ^ 1) * 512;
                float* Bd = BF + (p ^ 1) * 1024;
                Ad[(gkf + 0) * 64 + growf] = an.x;
                Ad[(gkf + 1) * 64 + growf] = an.y;
                Ad[(gkf + 2) * 64 + growf] = an.z;
                Ad[(gkf + 3) * 64 + growf] = an.w;
                *reinterpret_cast<float4*>(&Bd[browf * 128 + bcolf]) = bn0;
                *reinterpret_cast<float4*>(&Bd[browf * 128 + bcolf + 4]) = bn1;
                BARF();
                p ^= 1;
            }
        }

        // -------- epilogue1: h1 -> HF, stage W2 chunk 0 --------
        {
#pragma unroll
            for (int i = 0; i < 8; i++) {
                int row = fty8 + i;
                float dd = s_dist_f[row];
#pragma unroll
                for (int j = 0; j < 4; j++) {
                    int col = cAf + 2 * j;
                    int swz = ((col >> 2) & 7) << 3;
                    float2 v = acc[i][j];
                    v.x = silu(v.x + dd * s_w256[col] + s_b1[col]);
                    v.y = silu(v.y + dd * s_w256[col + 1] + s_b1[col + 1]);
                    HF[col * 64 + (row ^ swz)] = v.x;
                    HF[(col + 1) * 64 + (row ^ swz)] = v.y;
                    acc[i][j] = make_float2(0.f, 0.f);
                }
            }
            float4 b0 = *reinterpret_cast<const float4*>(&W2[browf * HID + bcolf]);
            float4 b1v = *reinterpret_cast<const float4*>(&W2[browf * HID + bcolf + 4]);
            *reinterpret_cast<float4*>(&BF[browf * 128 + bcolf]) = b0;
            *reinterpret_cast<float4*>(&BF[browf * 128 + bcolf + 4]) = b1v;
        }
        BARF();

        // -------- GEMM2: K=128 (A from HF swizzled) --------
        int q = 0;
#pragma unroll 1
        for (int kb = 0; kb < 128; kb += 8) {
            float4 bn0, bn1;
            const bool hn = (kb + 8) < 128;
            if (hn) {
                bn0 = *reinterpret_cast<const float4*>(&W2[(kb + 8 + browf) * HID + bcolf]);
                bn1 = *reinterpret_cast<const float4*>(&W2[(kb + 8 + browf) * HID + bcolf + 4]);
            }
            const float* Bb = BF + q * 1024;
#pragma unroll
            for (int kk = 0; kk < 8; kk++) {
                int k = kb + kk;
                int swz = ((k >> 2) & 7) << 3;
                float4 a0 = *reinterpret_cast<const float4*>(&HF[k * 64 + (fty8 ^ swz)]);
                float4 a1 = *reinterpret_cast<const float4*>(&HF[k * 64 + (fty8 ^ swz) + 4]);
                float4 b0 = *reinterpret_cast<const float4*>(&Bb[kk * 128 + cAf]);
                float4 b1v = *reinterpret_cast<const float4*>(&Bb[kk * 128 + cAf + 4]);
                float  ar[8]  = {a0.x, a0.y, a0.z, a0.w, a1.x, a1.y, a1.z, a1.w};
                float2 bp2[4] = {{b0.x, b0.y}, {b0.z, b0.w}, {b1v.x, b1v.y}, {b1v.z, b1v.w}};
#pragma unroll
                for (int i = 0; i < 8; i++) {
                    float2 ap = make_float2(ar[i], ar[i]);
#pragma unroll
                    for (int j = 0; j < 4; j++) acc[i][j] = ffma2(ap, bp2[j], acc[i][j]);
                }
            }
            if (hn) {
                float* Bd = BF + (q ^ 1) * 1024;
                *reinterpret_cast<float4*>(&Bd[browf * 128 + bcolf]) = bn0;
                *reinterpret_cast<float4*>(&Bd[browf * 128 + bcolf + 4]) = bn1;
                BARF();
                q ^= 1;
            }
        }
        BARF();   // all HF reads done before overwrite

        // -------- epilogue2: h2 -> HF --------
#pragma unroll
        for (int i = 0; i < 8; i++) {
            int row = fty8 + i;
#pragma unroll
            for (int j = 0; j < 4; j++) {
                int col = cAf + 2 * j;
                int swz = ((col >> 2) & 7) << 3;
                float2 v = acc[i][j];
                v.x = silu(v.x + s_b2[col]);
                v.y = silu(v.y + s_b2[col + 1]);
                HF[col * 64 + (row ^ swz)] = v.x;
                HF[(col + 1) * 64 + (row ^ swz)] = v.y;
            }
        }
        BARF();

        // -------- GEMM3 --------
        {
            int e  = ft >> 1;             // 0..63
            int c0 = (ft & 1) << 1;       // 0 or 2
            float s0 = b3s[c0], s1 = b3s[c0 + 1];
#pragma unroll 8
            for (int k = 0; k < 128; k++) {
                int swz = ((k >> 2) & 7) << 3;
                float h = HF[k * 64 + (e ^ swz)];
                s0 += h * w3s[k * 4 + c0];
                s1 += h * w3s[k * 4 + c0 + 1];
            }
            int ge = tile0 + 128 + e;
            if (ge < E)
                *reinterpret_cast<float2*>(&out[ge * 4 + c0]) = make_float2(s0, s1);
        }
    }
}

// ---------------------------------------------------------------------------
extern "C" void kernel_launch(void* const* d_in, const int* in_sizes, int n_in,
                              void* d_out, int out_size) {
    const float* x   = (const float*)d_in[0];
    const float* pos = (const float*)d_in[1];
    const int*   ei  = (const int*)  d_in[2];
    const float* Wa  = (const float*)d_in[3];
    const float* ba  = (const float*)d_in[4];
    const float* Wp  = (const float*)d_in[5];
    const float* bp  = (const float*)d_in[6];
    const float* W1  = (const float*)d_in[7];
    const float* b1  = (const float*)d_in[8];
    const float* W2  = (const float*)d_in[9];
    const float* b2  = (const float*)d_in[10];
    const float* W3  = (const float*)d_in[11];
    const float* b3  = (const float*)d_in[12];
    float* out = (float*)d_out;

    int N = in_sizes[0] / 16;
    int E = in_sizes[2] / 2;

    size_t smem_bytes = (size_t)(35840 + 1476) * sizeof(float);
    cudaFuncSetAttribute(edge_mlp_hybrid,
                         cudaFuncAttributeMaxDynamicSharedMemorySize,
                         (int)smem_bytes);

    node_emb_kernel<<<(N + NPB - 1) / NPB, 128>>>(x, pos, Wa, ba, Wp, bp, N);
    prep_weights<<<12, 256>>>(W1, W2);
    edge_mlp_hybrid<<<(E + TILE - 1) / TILE, THREADS, smem_bytes>>>(
        pos, ei, W1, b1, W2, b2, W3, b3, out, E);
}

// round 6
// speedup vs baseline: 3.2301x; 3.2301x over previous
#include <cuda_runtime.h>
#include <cuda_fp16.h>
#include <math.h>
#include <stdint.h>

#define HID 128
#define BM  256
#define THREADS 512
#define NPB 32
#define N_NODES_MAX 100000

__device__ __half g_node_emb[N_NODES_MAX * HID];
__device__ __half g_w1h[8 * 4096];   // W1 chunks, fp16 fragment-major
__device__ __half g_w2h[4 * 4096];   // W2 chunks

__device__ __forceinline__ float silu(float v) {
    return __fdividef(v, 1.0f + __expf(-v));
}
__device__ __forceinline__ void mma16(float4& d, uint32_t a0, uint32_t a1,
                                      uint32_t a2, uint32_t a3,
                                      uint32_t b0, uint32_t b1) {
    asm volatile(
        "mma.sync.aligned.m16n8k16.row.col.f32.f16.f16.f32 "
        "{%0,%1,%2,%3},{%4,%5,%6,%7},{%8,%9},{%0,%1,%2,%3};"
        : "+f"(d.x), "+f"(d.y), "+f"(d.z), "+f"(d.w)
        : "r"(a0), "r"(a1), "r"(a2), "r"(a3), "r"(b0), "r"(b1));
}
__device__ __forceinline__ void ldm4(uint32_t& a0, uint32_t& a1,
                                     uint32_t& a2, uint32_t& a3, uint32_t addr) {
    asm volatile("ldmatrix.sync.aligned.m8n8.x4.shared.b16 {%0,%1,%2,%3},[%4];"
                 : "=r"(a0), "=r"(a1), "=r"(a2), "=r"(a3) : "r"(addr));
}

// A staging buffer (GEMM1): 256 rows x 32 halfs (64B/row); swizzled 16B chunks.
__device__ __forceinline__ int a_addr(int row, int cc) {
    int line = row >> 1;
    int off = ((row & 1) << 2) + cc;            // 0..7 within 128B line
    return line * 128 + ((off ^ (line & 7)) << 4);
}
// hs buffer: 256 rows x 128 halfs (256B/row); swizzled 16B chunks.
__device__ __forceinline__ int hs_pos(int row, int cc) {
    return (cc & 8) + ((cc & 7) ^ (row & 7));
}

// ------------------- Kernel A: node embeddings (fp16 out) -------------------
__global__ void node_emb_kernel(const float* __restrict__ x,
                                const float* __restrict__ pos,
                                const float* __restrict__ Wa,
                                const float* __restrict__ ba,
                                const float* __restrict__ Wp,
                                const float* __restrict__ bp, int N) {
    int j = threadIdx.x;
    float wa[16];
#pragma unroll
    for (int k = 0; k < 16; k++) wa[k] = Wa[k * HID + j];
    float wp[3];
#pragma unroll
    for (int k = 0; k < 3; k++) wp[k] = Wp[k * HID + j];
    float bb = ba[j] + bp[j];

    __shared__ float xs[NPB][16];
    __shared__ float ps[NPB][3];
    int n0 = blockIdx.x * NPB;
    for (int i = j; i < NPB * 16; i += 128) {
        int n = n0 + (i >> 4);
        xs[i >> 4][i & 15] = (n < N) ? x[n * 16 + (i & 15)] : 0.0f;
    }
    for (int i = j; i < NPB * 3; i += 128) {
        int n = n0 + i / 3;
        ps[i / 3][i % 3] = (n < N) ? pos[n * 3 + i % 3] : 0.0f;
    }
    __syncthreads();
    for (int n = 0; n < NPB; n++) {
        if (n0 + n >= N) break;
        float s = bb;
#pragma unroll
        for (int k = 0; k < 16; k++) s += xs[n][k] * wa[k];
#pragma unroll
        for (int k = 0; k < 3; k++) s += ps[n][k] * wp[k];
        g_node_emb[(n0 + n) * HID + j] = __float2half(s);
    }
}

// ------------- Kernel B: pack W1/W2 into fp16 fragment-major chunks --------
// per 32-k chunk (4096 halfs): idx = ((step*128 + n)*4 + t)*4 + u
//   u=0,1 -> k = step*16 + 2t + u ;  u=2,3 -> k = step*16 + 8 + 2t + (u-2)
__global__ void prep_weights(const float* __restrict__ W1,
                             const float* __restrict__ W2) {
    int c = blockIdx.x;                       // 0..7 -> W1, 8..11 -> W2
    const float* W = (c < 8) ? W1 : W2;
    int cc = (c < 8) ? c : c - 8;
    __half* dst = (c < 8) ? (g_w1h + c * 4096) : (g_w2h + (c - 8) * 4096);
    for (int idx = threadIdx.x; idx < 4096; idx += 256) {
        int u = idx & 3;
        int t = (idx >> 2) & 3;
        int n = (idx >> 4) & 127;
        int step = idx >> 11;
        int kl = step * 16 + ((u >> 1) << 3) + 2 * t + (u & 1);
        dst[idx] = __float2half(W[(cc * 32 + kl) * 128 + n]);
    }
}

// ------------------- Kernel C: fused edge MLP, fp16 mma ---------------------
__global__ void __launch_bounds__(THREADS, 1)
edge_mlp_fp16(const float* __restrict__ pos, const int* __restrict__ ei,
              const float* __restrict__ W1, const float* __restrict__ b1,
              const float* __restrict__ b2,
              const float* __restrict__ W3, const float* __restrict__ b3,
              float* __restrict__ out, int E) {
    extern __shared__ __align__(16) float sm[];
    float* X = sm;                  // 16512 floats: A dbl / hs / partials
    float* Y = sm + 16512;          // 4096 floats: B dbl (2 x 8KB)
    float* aux = sm + 16512 + 4096;
    int*   s_soff = (int*)aux;              // 256
    int*   s_doff = (int*)(aux + 256);      // 256
    float* s_dist = aux + 512;              // 256
    float* s_w256 = aux + 768;              // 128
    float* s_b1   = aux + 896;              // 128
    float* s_b2   = aux + 1024;             // 128
    float* w3s    = aux + 1152;             // 512
    float* b3s    = aux + 1664;             // 4

    __half* XH = (__half*)X;
    __half* YH = (__half*)Y;
    const uint32_t Xs = (uint32_t)__cvta_generic_to_shared(XH);

    const int tid  = threadIdx.x;
    const int lane = tid & 31;
    const int wid  = tid >> 5;
    const int m_warp = (wid >> 2) * 64;
    const int n_warp = (wid & 3) * 32;
    const int g = lane >> 2;
    const int t = lane & 3;
    const int tile0 = blockIdx.x * BM;

    // ---- setup ----
    if (tid < BM) {
        int ge = tile0 + tid; if (ge >= E) ge = E - 1;
        int s = ei[ge], d = ei[E + ge];
        s_soff[tid] = s * HID;
        s_doff[tid] = d * HID;
        float dx = pos[s * 3 + 0] - pos[d * 3 + 0];
        float dy = pos[s * 3 + 1] - pos[d * 3 + 1];
        float dz = pos[s * 3 + 2] - pos[d * 3 + 2];
        s_dist[tid] = sqrtf(dx * dx + dy * dy + dz * dz);
    } else if (tid < BM + 128) {
        int c = tid - BM;
        s_w256[c] = W1[256 * 128 + c];
        s_b1[c] = b1[c];
        s_b2[c] = b2[c];
    }
    for (int i = tid; i < 512; i += THREADS) w3s[i] = W3[i];
    if (tid < 4) b3s[tid] = b3[tid];
    __syncthreads();

    const int srow = tid >> 1;           // staging row 0..255
    const int ss   = tid & 1;            // k16 half within chunk
    const int srcOff = s_soff[srow];
    const int dstOff = s_doff[srow];

    float4 acc[4][4];
#pragma unroll
    for (int i = 0; i < 4; i++)
#pragma unroll
        for (int j = 0; j < 4; j++) acc[i][j] = make_float4(0.f, 0.f, 0.f, 0.f);

    // GEMM1 compute on buffer p
    auto compute1 = [&](int p) {
        const uint32_t abase = Xs + p * 16384;
        const __half* Bp = YH + p * 4096;
#pragma unroll
        for (int s = 0; s < 2; s++) {
            uint2 bf[4];
#pragma unroll
            for (int ni = 0; ni < 4; ni++) {
                int n = n_warp + ni * 8 + g;
                bf[ni] = *reinterpret_cast<const uint2*>(
                    Bp + (((s * 128 + n) << 2) + t) * 4);
            }
#pragma unroll
            for (int mi = 0; mi < 4; mi++) {
                int lrow = m_warp + mi * 16 + (lane & 7) + (lane & 8);
                int cc = s * 2 + (lane >> 4);
                uint32_t a0, a1, a2, a3;
                ldm4(a0, a1, a2, a3, abase + a_addr(lrow, cc));
#pragma unroll
                for (int ni = 0; ni < 4; ni++)
                    mma16(acc[mi][ni], a0, a1, a2, a3, bf[ni].x, bf[ni].y);
            }
        }
    };

    // ================= GEMM1: K=256 (gathered fp16 A) ======================
    {
        const __half* gp = g_node_emb + srcOff + ss * 16;
        uint4 av0 = *reinterpret_cast<const uint4*>(gp);
        uint4 av1 = *reinterpret_cast<const uint4*>(gp + 8);
        uint4 bv  = reinterpret_cast<const uint4*>(g_w1h)[tid];
        char* ab = (char*)XH;
        *reinterpret_cast<uint4*>(ab + a_addr(srow, ss * 2 + 0)) = av0;
        *reinterpret_cast<uint4*>(ab + a_addr(srow, ss * 2 + 1)) = av1;
        reinterpret_cast<uint4*>(YH)[tid] = bv;
    }
    __syncthreads();
    int p = 0;
#pragma unroll 1
    for (int c = 0; c < 8; c++) {
        uint4 av0, av1, bv;
        if (c < 8 - 1) {
            int cn = c + 1;
            int kb = (cn & 3) * 32 + ss * 16;
            const __half* gp = g_node_emb + ((cn < 4) ? srcOff : dstOff) + kb;
            av0 = *reinterpret_cast<const uint4*>(gp);
            av1 = *reinterpret_cast<const uint4*>(gp + 8);
            bv  = reinterpret_cast<const uint4*>(g_w1h + cn * 4096)[tid];
        }
        compute1(p);
        if (c < 8 - 1) {
            char* ab = (char*)XH + (p ^ 1) * 16384;
            *reinterpret_cast<uint4*>(ab + a_addr(srow, ss * 2 + 0)) = av0;
            *reinterpret_cast<uint4*>(ab + a_addr(srow, ss * 2 + 1)) = av1;
            reinterpret_cast<uint4*>(YH + (p ^ 1) * 4096)[tid] = bv;
            __syncthreads();
            p ^= 1;
        }
    }
    __syncthreads();   // all A/B buffer reads done before hs overwrite

    // ---- epilogue1: h1 = fp16(silu(D1 + dist*w256 + b1)) -> hs ------------
    {
        uint4 w2v = reinterpret_cast<const uint4*>(g_w2h)[tid];
        char* hb = (char*)XH;
#pragma unroll
        for (int mi = 0; mi < 4; mi++) {
            int r = m_warp + mi * 16 + g;
            float d0 = s_dist[r], d1 = s_dist[r + 8];
#pragma unroll
            for (int ni = 0; ni < 4; ni++) {
                int c0 = n_warp + ni * 8 + 2 * t;
                float w0 = s_w256[c0], w1 = s_w256[c0 + 1];
                float bb0 = s_b1[c0], bb1 = s_b1[c0 + 1];
                float4 a = acc[mi][ni];
                __half2 lo = __floats2half2_rn(silu(a.x + d0 * w0 + bb0),
                                               silu(a.y + d0 * w1 + bb1));
                __half2 hi = __floats2half2_rn(silu(a.z + d1 * w0 + bb0),
                                               silu(a.w + d1 * w1 + bb1));
                int cc = c0 >> 3;
                int boff = (c0 & 7) * 2;
                *reinterpret_cast<uint32_t*>(hb + r * 256 + hs_pos(r, cc) * 16 + boff) =
                    *reinterpret_cast<uint32_t*>(&lo);
                *reinterpret_cast<uint32_t*>(hb + (r + 8) * 256 + hs_pos(r + 8, cc) * 16 + boff) =
                    *reinterpret_cast<uint32_t*>(&hi);
                acc[mi][ni] = make_float4(0.f, 0.f, 0.f, 0.f);
            }
        }
        reinterpret_cast<uint4*>(YH)[tid] = w2v;
    }
    __syncthreads();

    // ================= GEMM2: h1 @ W2, K=128 ================================
    int q = 0;
#pragma unroll 1
    for (int c = 0; c < 4; c++) {
        uint4 bv;
        if (c < 3) bv = reinterpret_cast<const uint4*>(g_w2h + (c + 1) * 4096)[tid];
        {
            const __half* Bp = YH + q * 4096;
#pragma unroll
            for (int s = 0; s < 2; s++) {
                int sg = c * 2 + s;     // global k16 index 0..7
                uint2 bf[4];
#pragma unroll
                for (int ni = 0; ni < 4; ni++) {
                    int n = n_warp + ni * 8 + g;
                    bf[ni] = *reinterpret_cast<const uint2*>(
                        Bp + (((s * 128 + n) << 2) + t) * 4);
                }
#pragma unroll
                for (int mi = 0; mi < 4; mi++) {
                    int lrow = m_warp + mi * 16 + (lane & 7) + (lane & 8);
                    int cc = sg * 2 + (lane >> 4);
                    uint32_t addr = Xs + lrow * 256 + hs_pos(lrow, cc) * 16;
                    uint32_t a0, a1, a2, a3;
                    ldm4(a0, a1, a2, a3, addr);
#pragma unroll
                    for (int ni = 0; ni < 4; ni++)
                        mma16(acc[mi][ni], a0, a1, a2, a3, bf[ni].x, bf[ni].y);
                }
            }
        }
        if (c < 3) {
            reinterpret_cast<uint4*>(YH + (q ^ 1) * 4096)[tid] = bv;
            __syncthreads();
            q ^= 1;
        }
    }
    __syncthreads();   // all hs reads done before partials overwrite

    // ---- epilogue2: silu(D2+b2) -> GEMM3 partials -> reduce ----------------
    {
        const int cid = (wid & 3) * 4 + t;
#pragma unroll
        for (int mi = 0; mi < 4; mi++) {
            int r = m_warp + mi * 16 + g;
            float4 plo = make_float4(0.f, 0.f, 0.f, 0.f);
            float4 phi = make_float4(0.f, 0.f, 0.f, 0.f);
#pragma unroll
            for (int ni = 0; ni < 4; ni++) {
                int c0 = n_warp + ni * 8 + 2 * t;
                float4 a = acc[mi][ni];
                float v0 = silu(a.x + s_b2[c0]);
                float v1 = silu(a.y + s_b2[c0 + 1]);
                float v2 = silu(a.z + s_b2[c0]);
                float v3 = silu(a.w + s_b2[c0 + 1]);
                float4 w0 = *reinterpret_cast<const float4*>(&w3s[c0 * 4]);
                float4 w1 = *reinterpret_cast<const float4*>(&w3s[(c0 + 1) * 4]);
                plo.x += v0 * w0.x + v1 * w1.x;
                plo.y += v0 * w0.y + v1 * w1.y;
                plo.z += v0 * w0.z + v1 * w1.z;
                plo.w += v0 * w0.w + v1 * w1.w;
                phi.x += v2 * w0.x + v3 * w1.x;
                phi.y += v2 * w0.y + v3 * w1.y;
                phi.z += v2 * w0.z + v3 * w1.z;
                phi.w += v2 * w0.w + v3 * w1.w;
            }
            *reinterpret_cast<float4*>(&X[cid * 1032 + r * 4]) = plo;
            *reinterpret_cast<float4*>(&X[cid * 1032 + (r + 8) * 4]) = phi;
        }
    }
    __syncthreads();
    if (tid < BM) {
        float4 o = make_float4(b3s[0], b3s[1], b3s[2], b3s[3]);
#pragma unroll
        for (int cid = 0; cid < 16; cid++) {
            float4 pv = *reinterpret_cast<const float4*>(&X[cid * 1032 + tid * 4]);
            o.x += pv.x; o.y += pv.y; o.z += pv.z; o.w += pv.w;
        }
        int ge = tile0 + tid;
        if (ge < E) *reinterpret_cast<float4*>(&out[ge * 4]) = o;
    }
}

// ---------------------------------------------------------------------------
extern "C" void kernel_launch(void* const* d_in, const int* in_sizes, int n_in,
                              void* d_out, int out_size) {
    const float* x   = (const float*)d_in[0];
    const float* pos = (const float*)d_in[1];
    const int*   ei  = (const int*)  d_in[2];
    const float* Wa  = (const float*)d_in[3];
    const float* ba  = (const float*)d_in[4];
    const float* Wp  = (const float*)d_in[5];
    const float* bp  = (const float*)d_in[6];
    const float* W1  = (const float*)d_in[7];
    const float* b1  = (const float*)d_in[8];
    const float* W2  = (const float*)d_in[9];
    const float* b2  = (const float*)d_in[10];
    const float* W3  = (const float*)d_in[11];
    const float* b3  = (const float*)d_in[12];
    float* out = (float*)d_out;

    int N = in_sizes[0] / 16;
    int E = in_sizes[2] / 2;

    // smem: X 16512 + Y 4096 + aux 1668 floats = 89104 bytes
    size_t smem_bytes = (size_t)(16512 + 4096 + 1668) * sizeof(float);
    cudaFuncSetAttribute(edge_mlp_fp16,
                         cudaFuncAttributeMaxDynamicSharedMemorySize,
                         (int)smem_bytes);

    node_emb_kernel<<<(N + NPB - 1) / NPB, 128>>>(x, pos, Wa, ba, Wp, bp, N);
    prep_weights<<<12, 256>>>(W1, W2);
    edge_mlp_fp16<<<(E + BM - 1) / BM, THREADS, smem_bytes>>>(
        pos, ei, W1, b1, b2, W3, b3, out, E);
}

// round 7
// speedup vs baseline: 4.3511x; 1.3470x over previous
#include <cuda_runtime.h>
#include <cuda_fp16.h>
#include <math.h>
#include <stdint.h>

#define HID 128
#define BM  128
#define THREADS 256
#define NPB 32
#define N_NODES_MAX 100000

__device__ __half g_hsrc[N_NODES_MAX * HID];   // node_emb @ W1[0:128]
__device__ __half g_htgt[N_NODES_MAX * HID];   // node_emb @ W1[128:256]
__device__ __half g_w2h[4 * 4096];             // W2 chunks, fragment-major
__device__ float  g_wx[2][16 * 128];           // (Wa @ W1part)
__device__ float  g_wp[2][3 * 128];            // (Wp @ W1part)
__device__ float  g_cb[2][128];                // (ba+bp) @ W1part

__device__ __forceinline__ float silu(float v) {
    return __fdividef(v, 1.0f + __expf(-v));
}
__device__ __forceinline__ void mma16(float4& d, uint32_t a0, uint32_t a1,
                                      uint32_t a2, uint32_t a3,
                                      uint32_t b0, uint32_t b1) {
    asm volatile(
        "mma.sync.aligned.m16n8k16.row.col.f32.f16.f16.f32 "
        "{%0,%1,%2,%3},{%4,%5,%6,%7},{%8,%9},{%0,%1,%2,%3};"
        : "+f"(d.x), "+f"(d.y), "+f"(d.z), "+f"(d.w)
        : "r"(a0), "r"(a1), "r"(a2), "r"(a3), "r"(b0), "r"(b1));
}
__device__ __forceinline__ void ldm4(uint32_t& a0, uint32_t& a1,
                                     uint32_t& a2, uint32_t& a3, uint32_t addr) {
    asm volatile("ldmatrix.sync.aligned.m8n8.x4.shared.b16 {%0,%1,%2,%3},[%4];"
                 : "=r"(a0), "=r"(a1), "=r"(a2), "=r"(a3) : "r"(addr));
}
// hs buffer: 128 rows x 128 halfs (256B/row); swizzled 16B chunks.
__device__ __forceinline__ int hs_pos(int row, int cc) {
    return (cc & 8) + ((cc & 7) ^ (row & 7));
}

// ------------- Kernel 1: weight products (fp32, tiny) -----------------------
__global__ void weight_prod(const float* __restrict__ Wa,
                            const float* __restrict__ ba,
                            const float* __restrict__ Wp,
                            const float* __restrict__ bp,
                            const float* __restrict__ W1) {
    __shared__ float swa[16 * 128];
    __shared__ float swp[3 * 128];
    __shared__ float sb[128];
    int p = blockIdx.x;      // 0 = src part (W1 rows 0..127), 1 = tgt part
    int j = threadIdx.x;     // 0..127
    for (int i = j; i < 16 * 128; i += 128) swa[i] = Wa[i];
    for (int i = j; i < 3 * 128; i += 128) swp[i] = Wp[i];
    sb[j] = ba[j] + bp[j];
    __syncthreads();

    float ax[16];
#pragma unroll
    for (int i = 0; i < 16; i++) ax[i] = 0.f;
    float ap[3] = {0.f, 0.f, 0.f};
    float ac = 0.f;
    for (int k = 0; k < 128; k++) {
        float w = W1[(p * 128 + k) * 128 + j];
#pragma unroll
        for (int i = 0; i < 16; i++) ax[i] += swa[i * 128 + k] * w;
#pragma unroll
        for (int i = 0; i < 3; i++) ap[i] += swp[i * 128 + k] * w;
        ac += sb[k] * w;
    }
#pragma unroll
    for (int i = 0; i < 16; i++) g_wx[p][i * 128 + j] = ax[i];
#pragma unroll
    for (int i = 0; i < 3; i++) g_wp[p][i * 128 + j] = ap[i];
    g_cb[p][j] = ac;
}

// ------------- Kernel 2: per-node h_src / h_tgt (fp32 math, fp16 store) ----
__global__ void node_h_kernel(const float* __restrict__ x,
                              const float* __restrict__ pos, int N) {
    int j = threadIdx.x;  // 0..127
    float wx0[16], wx1[16], wp0[3], wp1[3];
#pragma unroll
    for (int i = 0; i < 16; i++) {
        wx0[i] = g_wx[0][i * 128 + j];
        wx1[i] = g_wx[1][i * 128 + j];
    }
#pragma unroll
    for (int i = 0; i < 3; i++) {
        wp0[i] = g_wp[0][i * 128 + j];
        wp1[i] = g_wp[1][i * 128 + j];
    }
    float c0 = g_cb[0][j], c1 = g_cb[1][j];

    __shared__ float xs[NPB][16];
    __shared__ float ps[NPB][3];
    int n0 = blockIdx.x * NPB;
    for (int i = j; i < NPB * 16; i += 128) {
        int n = n0 + (i >> 4);
        xs[i >> 4][i & 15] = (n < N) ? x[n * 16 + (i & 15)] : 0.0f;
    }
    for (int i = j; i < NPB * 3; i += 128) {
        int n = n0 + i / 3;
        ps[i / 3][i % 3] = (n < N) ? pos[n * 3 + i % 3] : 0.0f;
    }
    __syncthreads();
    for (int n = 0; n < NPB; n++) {
        if (n0 + n >= N) break;
        float s0 = c0, s1 = c1;
#pragma unroll
        for (int i = 0; i < 16; i++) {
            s0 += xs[n][i] * wx0[i];
            s1 += xs[n][i] * wx1[i];
        }
#pragma unroll
        for (int i = 0; i < 3; i++) {
            s0 += ps[n][i] * wp0[i];
            s1 += ps[n][i] * wp1[i];
        }
        g_hsrc[(n0 + n) * HID + j] = __float2half(s0);
        g_htgt[(n0 + n) * HID + j] = __float2half(s1);
    }
}

// ------------- Kernel 3: pack W2 into fp16 fragment-major chunks -----------
__global__ void prep_w2(const float* __restrict__ W2) {
    int c = blockIdx.x;   // 0..3
    __half* dst = g_w2h + c * 4096;
    for (int idx = threadIdx.x; idx < 4096; idx += 256) {
        int u = idx & 3;
        int t = (idx >> 2) & 3;
        int n = (idx >> 4) & 127;
        int step = idx >> 11;
        int kl = step * 16 + ((u >> 1) << 3) + 2 * t + (u & 1);
        dst[idx] = __float2half(W2[(c * 32 + kl) * 128 + n]);
    }
}

// ------------- Kernel 4: edge MLP: gather+silu -> GEMM2 -> GEMM3 -----------
__global__ void __launch_bounds__(THREADS, 2)
edge_mlp2(const float* __restrict__ pos, const int* __restrict__ ei,
          const float* __restrict__ W1, const float* __restrict__ b1,
          const float* __restrict__ b2,
          const float* __restrict__ W3, const float* __restrict__ b3,
          float* __restrict__ out, int E) {
    extern __shared__ __align__(16) float sm[];
    float* X = sm;                  // 8256 floats: hs (8192) / partials (8256)
    float* Y = sm + 8256;           // 4096 floats: B dbl buf (2 x 4096 halfs)
    float* aux = sm + 8256 + 4096;
    int*   s_soff = (int*)aux;              // 128
    int*   s_doff = (int*)(aux + 128);      // 128
    float* s_dist = aux + 256;              // 128
    float* s_w256 = aux + 384;              // 128
    float* s_b1   = aux + 512;              // 128
    float* s_b2   = aux + 640;              // 128
    float* w3s    = aux + 768;              // 512
    float* b3s    = aux + 1280;             // 4

    __half* XH = (__half*)X;
    __half* YH = (__half*)Y;
    const uint32_t Xs = (uint32_t)__cvta_generic_to_shared(XH);

    const int tid  = threadIdx.x;
    const int lane = tid & 31;
    const int wid  = tid >> 5;              // 0..7
    const int m_warp = (wid >> 2) * 64;     // 0 / 64
    const int n_warp = (wid & 3) * 32;
    const int g = lane >> 2;
    const int t = lane & 3;
    const int tile0 = blockIdx.x * BM;

    // ---- setup ----
    if (tid < BM) {
        int ge = tile0 + tid; if (ge >= E) ge = E - 1;
        int s = ei[ge], d = ei[E + ge];
        s_soff[tid] = s * HID;
        s_doff[tid] = d * HID;
        float dx = pos[s * 3 + 0] - pos[d * 3 + 0];
        float dy = pos[s * 3 + 1] - pos[d * 3 + 1];
        float dz = pos[s * 3 + 2] - pos[d * 3 + 2];
        s_dist[tid] = sqrtf(dx * dx + dy * dy + dz * dz);
    } else {
        int c = tid - BM;
        s_w256[c] = W1[256 * 128 + c];
        s_b1[c] = b1[c];
        s_b2[c] = b2[c];
    }
    for (int i = tid; i < 512; i += THREADS) w3s[i] = W3[i];
    if (tid < 4) b3s[tid] = b3[tid];
    __syncthreads();

    // ---- phase 1: gather h parts, h1 = silu(hsrc+htgt+dist*w256+b1) -------
    {
        const int row = tid >> 1;
        const int half = tid & 1;
        const float dd = s_dist[row];
        const __half* ps_ = g_hsrc + s_soff[row] + half * 64;
        const __half* pt_ = g_htgt + s_doff[row] + half * 64;
        char* hb = (char*)XH;
#pragma unroll
        for (int u = 0; u < 8; u++) {
            uint4 av = *reinterpret_cast<const uint4*>(ps_ + u * 8);
            uint4 bv = *reinterpret_cast<const uint4*>(pt_ + u * 8);
            int c0 = half * 64 + u * 8;
            float4 wA = *reinterpret_cast<const float4*>(&s_w256[c0]);
            float4 wB = *reinterpret_cast<const float4*>(&s_w256[c0 + 4]);
            float4 bA = *reinterpret_cast<const float4*>(&s_b1[c0]);
            float4 bB = *reinterpret_cast<const float4*>(&s_b1[c0 + 4]);
            const __half2* ah = reinterpret_cast<const __half2*>(&av);
            const __half2* bh = reinterpret_cast<const __half2*>(&bv);
            float2 f0 = __half22float2(ah[0]), g0 = __half22float2(bh[0]);
            float2 f1 = __half22float2(ah[1]), g1 = __half22float2(bh[1]);
            float2 f2 = __half22float2(ah[2]), g2 = __half22float2(bh[2]);
            float2 f3 = __half22float2(ah[3]), g3 = __half22float2(bh[3]);
            __half2 o0 = __floats2half2_rn(
                silu(f0.x + g0.x + dd * wA.x + bA.x),
                silu(f0.y + g0.y + dd * wA.y + bA.y));
            __half2 o1 = __floats2half2_rn(
                silu(f1.x + g1.x + dd * wA.z + bA.z),
                silu(f1.y + g1.y + dd * wA.w + bA.w));
            __half2 o2 = __floats2half2_rn(
                silu(f2.x + g2.x + dd * wB.x + bB.x),
                silu(f2.y + g2.y + dd * wB.y + bB.y));
            __half2 o3 = __floats2half2_rn(
                silu(f3.x + g3.x + dd * wB.z + bB.z),
                silu(f3.y + g3.y + dd * wB.w + bB.w));
            uint4 ov;
            ov.x = *reinterpret_cast<uint32_t*>(&o0);
            ov.y = *reinterpret_cast<uint32_t*>(&o1);
            ov.z = *reinterpret_cast<uint32_t*>(&o2);
            ov.w = *reinterpret_cast<uint32_t*>(&o3);
            int cc = half * 8 + u;
            *reinterpret_cast<uint4*>(hb + row * 256 + hs_pos(row, cc) * 16) = ov;
        }
        // stage W2 chunk 0
        const uint4* s4 = reinterpret_cast<const uint4*>(g_w2h);
        uint4* d4 = reinterpret_cast<uint4*>(YH);
        d4[tid] = s4[tid];
        d4[tid + 256] = s4[tid + 256];
    }
    __syncthreads();

    float4 acc[4][4];
#pragma unroll
    for (int i = 0; i < 4; i++)
#pragma unroll
        for (int j = 0; j < 4; j++) acc[i][j] = make_float4(0.f, 0.f, 0.f, 0.f);

    // ---- GEMM2: h1 @ W2, K=128, 4 chunks double-buffered -------------------
    int q = 0;
#pragma unroll 1
    for (int c = 0; c < 4; c++) {
        uint4 bv0, bv1;
        if (c < 3) {
            const uint4* s4 = reinterpret_cast<const uint4*>(g_w2h + (c + 1) * 4096);
            bv0 = s4[tid]; bv1 = s4[tid + 256];
        }
        {
            const __half* Bp = YH + q * 4096;
#pragma unroll
            for (int s = 0; s < 2; s++) {
                int sg = c * 2 + s;      // global k16 index 0..7
                uint2 bf[4];
#pragma unroll
                for (int ni = 0; ni < 4; ni++) {
                    int n = n_warp + ni * 8 + g;
                    bf[ni] = *reinterpret_cast<const uint2*>(
                        Bp + (((s * 128 + n) << 2) + t) * 4);
                }
#pragma unroll
                for (int mi = 0; mi < 4; mi++) {
                    int lrow = m_warp + mi * 16 + (lane & 7) + (lane & 8);
                    int cc = sg * 2 + (lane >> 4);
                    uint32_t addr = Xs + lrow * 256 + hs_pos(lrow, cc) * 16;
                    uint32_t a0, a1, a2, a3;
                    ldm4(a0, a1, a2, a3, addr);
#pragma unroll
                    for (int ni = 0; ni < 4; ni++)
                        mma16(acc[mi][ni], a0, a1, a2, a3, bf[ni].x, bf[ni].y);
                }
            }
        }
        if (c < 3) {
            uint4* d4 = reinterpret_cast<uint4*>(YH + (q ^ 1) * 4096);
            d4[tid] = bv0; d4[tid + 256] = bv1;
            __syncthreads();
            q ^= 1;
        }
    }
    __syncthreads();   // all hs reads done before partials overwrite

    // ---- epilogue2: silu(D2+b2) -> GEMM3 partials -> reduce ----------------
    {
        const int cid = (wid & 3) * 4 + t;
#pragma unroll
        for (int mi = 0; mi < 4; mi++) {
            int r = m_warp + mi * 16 + g;
            float4 plo = make_float4(0.f, 0.f, 0.f, 0.f);
            float4 phi = make_float4(0.f, 0.f, 0.f, 0.f);
#pragma unroll
            for (int ni = 0; ni < 4; ni++) {
                int c0 = n_warp + ni * 8 + 2 * t;
                float4 a = acc[mi][ni];
                float v0 = silu(a.x + s_b2[c0]);
                float v1 = silu(a.y + s_b2[c0 + 1]);
                float v2 = silu(a.z + s_b2[c0]);
                float v3 = silu(a.w + s_b2[c0 + 1]);
                float4 w0 = *reinterpret_cast<const float4*>(&w3s[c0 * 4]);
                float4 w1 = *reinterpret_cast<const float4*>(&w3s[(c0 + 1) * 4]);
                plo.x += v0 * w0.x + v1 * w1.x;
                plo.y += v0 * w0.y + v1 * w1.y;
                plo.z += v0 * w0.z + v1 * w1.z;
                plo.w += v0 * w0.w + v1 * w1.w;
                phi.x += v2 * w0.x + v3 * w1.x;
                phi.y += v2 * w0.y + v3 * w1.y;
                phi.z += v2 * w0.z + v3 * w1.z;
                phi.w += v2 * w0.w + v3 * w1.w;
            }
            *reinterpret_cast<float4*>(&X[cid * 516 + r * 4]) = plo;
            *reinterpret_cast<float4*>(&X[cid * 516 + (r + 8) * 4]) = phi;
        }
    }
    __syncthreads();
    if (tid < BM) {
        float4 o = make_float4(b3s[0], b3s[1], b3s[2], b3s[3]);
#pragma unroll
        for (int cid = 0; cid < 16; cid++) {
            float4 pv = *reinterpret_cast<const float4*>(&X[cid * 516 + tid * 4]);
            o.x += pv.x; o.y += pv.y; o.z += pv.z; o.w += pv.w;
        }
        int ge = tile0 + tid;
        if (ge < E) *reinterpret_cast<float4*>(&out[ge * 4]) = o;
    }
}

// ---------------------------------------------------------------------------
extern "C" void kernel_launch(void* const* d_in, const int* in_sizes, int n_in,
                              void* d_out, int out_size) {
    const float* x   = (const float*)d_in[0];
    const float* pos = (const float*)d_in[1];
    const int*   ei  = (const int*)  d_in[2];
    const float* Wa  = (const float*)d_in[3];
    const float* ba  = (const float*)d_in[4];
    const float* Wp  = (const float*)d_in[5];
    const float* bp  = (const float*)d_in[6];
    const float* W1  = (const float*)d_in[7];
    const float* b1  = (const float*)d_in[8];
    const float* W2  = (const float*)d_in[9];
    const float* b2  = (const float*)d_in[10];
    const float* W3  = (const float*)d_in[11];
    const float* b3  = (const float*)d_in[12];
    float* out = (float*)d_out;

    int N = in_sizes[0] / 16;
    int E = in_sizes[2] / 2;

    // smem: X 8256 + Y 4096 + aux 1284 floats = 54544 bytes
    size_t smem_bytes = (size_t)(8256 + 4096 + 1284) * sizeof(float);
    cudaFuncSetAttribute(edge_mlp2,
                         cudaFuncAttributeMaxDynamicSharedMemorySize,
                         (int)smem_bytes);

    weight_prod<<<2, 128>>>(Wa, ba, Wp, bp, W1);
    prep_w2<<<4, 256>>>(W2);
    node_h_kernel<<<(N + NPB - 1) / NPB, 128>>>(x, pos, N);
    edge_mlp2<<<(E + BM - 1) / BM, THREADS, smem_bytes>>>(
        pos, ei, W1, b1, b2, W3, b3, out, E);
}